// round 15
// baseline (speedup 1.0000x reference)
#include <cuda_runtime.h>
#include <math.h>

#define LTOT  13326
#define LPAD2 14464
#define NQ    4096
#define GUARD 4096
#define NG8   (LPAD2/8)
#define NSPLIT 16
#define KSPL  (LPAD2/NSPLIT)   // 904

__constant__ int   c_off [5] = {0, 4096, 7345, 9946, 11882};
__constant__ int   c_off2[5] = {0, 4368, 7856, 10672, 12800};
__constant__ int   c_ws  [5] = {64, 57, 51, 44, 38};
__constant__ float c_ratio[5]= {1.0f, 63.0f/56.0f, 63.0f/50.0f, 63.0f/43.0f, 63.0f/37.0f};

__device__ __align__(16) float g_mb  [2*32*NQ];
__device__ __align__(16) float g_m   [(size_t)2*32*LPAD2];
__device__ __align__(16) float g_base[(size_t)2*64*LPAD2];
__device__ __align__(16) float g_sq  [2*LPAD2];
__device__ __align__(16) float g_invb[(size_t)2*2*LPAD2];            // (10/nrm, bias)
__device__ __align__(16) float g_G   [(size_t)2*NQ*LPAD2 + 2*GUARD]; // H_P lives here
__device__ __align__(16) float g_P   [(size_t)2*NQ*LPAD2 + 2*GUARD]; // E
__device__ __align__(16) float g_H   [(size_t)2*NQ*LPAD2 + 2*GUARD]; // H_G
__device__ __align__(16) float g_invs[2*NQ];
__device__ __align__(16) float g_part[(size_t)NSPLIT*2*64*NQ];

__device__ __forceinline__ float cubw(float d) {
    d = fabsf(d);
    if (d <= 1.0f) return ((1.25f*d - 2.25f)*d)*d + 1.0f;
    if (d <  2.0f) return ((-0.75f*d + 3.75f)*d - 6.0f)*d + 3.0f;
    return 0.0f;
}
__device__ __forceinline__ float fexp(float x) {
    float t = fmaxf(x * 1.4426950408889634f, -125.0f);
    int   ri = __float2int_rn(t);
    float f  = t - (float)ri;
    float z  = f * 0.6931471805599453f;
    float p  = 1.0f + z*(1.0f + z*(0.5f + z*(0.16666667f + z*(0.041666667f + z*0.0083333333f))));
    return __int_as_float((ri + 127) << 23) * p;
}
__device__ __forceinline__ void ldwin8(const float* p, float w[8]) {
    int d = (int)((((size_t)p) >> 2) & 3);
    const float4* ap = (const float4*)(p - d);
    float4 A = ap[0], B = ap[1], C = B;
    if (d) C = ap[2];
    if (d == 0)      { w[0]=A.x;w[1]=A.y;w[2]=A.z;w[3]=A.w;w[4]=B.x;w[5]=B.y;w[6]=B.z;w[7]=B.w; }
    else if (d == 1) { w[0]=A.y;w[1]=A.z;w[2]=A.w;w[3]=B.x;w[4]=B.y;w[5]=B.z;w[6]=B.w;w[7]=C.x; }
    else if (d == 2) { w[0]=A.z;w[1]=A.w;w[2]=B.x;w[3]=B.y;w[4]=B.z;w[5]=B.w;w[6]=C.x;w[7]=C.y; }
    else             { w[0]=A.w;w[1]=B.x;w[2]=B.y;w[3]=B.z;w[4]=B.w;w[5]=C.x;w[6]=C.y;w[7]=C.z; }
}
__device__ __forceinline__ void ldwin4(const float* p, int o, float w[4]) {
    const float* ap = p + (o & ~3);
    int d = o & 3;
    float4 lo = *(const float4*)ap;
    if (d == 0) { w[0]=lo.x; w[1]=lo.y; w[2]=lo.z; w[3]=lo.w; return; }
    float4 hi = *(const float4*)(ap + 4);
    if (d == 1)      { w[0]=lo.y; w[1]=lo.z; w[2]=lo.w; w[3]=hi.x; }
    else if (d == 2) { w[0]=lo.z; w[1]=lo.w; w[2]=hi.x; w[3]=hi.y; }
    else             { w[0]=lo.w; w[1]=hi.x; w[2]=hi.y; w[3]=hi.z; }
}
__device__ __forceinline__ int stride_of(int l) {
    if (l < 4368)  return 66;
    if (l < 7856)  return 59;
    if (l < 10672) return 53;
    if (l < 12800) return 46;
    return 40;
}

// ---------------- zero m/base ----------------
__global__ void k_zero() {
    size_t i = (size_t)blockIdx.x*blockDim.x + threadIdx.x;
    size_t nm = (size_t)2*32*LPAD2/4, nb = (size_t)2*64*LPAD2/4;
    float4 z = make_float4(0.f,0.f,0.f,0.f);
    for (; i < nm + nb; i += (size_t)gridDim.x*blockDim.x) {
        if (i < nm) ((float4*)g_m)[i] = z;
        else ((float4*)g_base)[i - nm] = z;
    }
}

// ---------------- match_base ----------------
__global__ void k_matchbase(const float* __restrict__ inp, const float* __restrict__ Wb,
                            const float* __restrict__ bb, const float* __restrict__ ap) {
    int idx = blockIdx.x * blockDim.x + threadIdx.x;
    if (idx >= 2*32*4096) return;
    int pos = idx & 4095, cm = (idx >> 12) & 31, b = idx >> 17;
    const float* x = inp + ((size_t)b*64)*4096 + pos;
    const float* w = Wb + cm*64;
    float acc = bb[cm];
#pragma unroll
    for (int c = 0; c < 64; c++) acc = fmaf(w[c], x[(size_t)c*4096], acc);
    float a = ap[0];
    g_mb[idx] = acc >= 0.0f ? acc : a*acc;
}

// ---------------- resize + conv (padded layout) ----------------
__global__ __launch_bounds__(128) void k_resize_conv(const float* __restrict__ ref,
        const float* __restrict__ Wm, const float* __restrict__ bmv,
        const float* __restrict__ Wa, const float* __restrict__ bav,
        const float* __restrict__ ap) {
    __shared__ float Wsh[96][65];
    __shared__ float bsh[96];
    __shared__ float rv[8][65];
    __shared__ int   l2sh[8];
    int b = blockIdx.y, t = threadIdx.x;
    for (int i = t; i < 96*64; i += 128) {
        int o = i >> 6, c = i & 63;
        Wsh[o][c] = (o < 32) ? Wm[o*64 + c] : Wa[(o-32)*64 + c];
    }
    if (t < 96) bsh[t] = (t < 32) ? bmv[t] : bav[t-32];
    float a = ap[0];
    int p0 = blockIdx.x * 8;
    if (t < 8) {
        int pos = p0 + t, v = -1;
        if (pos < LTOT) {
            int s = 0;
            while (s < 4 && pos >= c_off[s+1]) s++;
            int ws = c_ws[s], lp = pos - c_off[s];
            int y = lp / ws, x = lp - y*ws;
            v = c_off2[s] + (y+1)*(ws+2) + (x+1);
        }
        l2sh[t] = v;
    }
    for (int i = t; i < 512; i += 128) {
        int c = i >> 3, pi = i & 7;
        int pos = p0 + pi;
        float val = 0.0f;
        if (pos < LTOT) {
            int s = 0;
            while (s < 4 && pos >= c_off[s+1]) s++;
            int lp = pos - c_off[s];
            int ws = c_ws[s];
            int y = lp / ws, x = lp - y*ws;
            float ry = (float)y * c_ratio[s], rx = (float)x * c_ratio[s];
            int iy0 = (int)floorf(ry); float fy = ry - (float)iy0;
            int ix0 = (int)floorf(rx); float fx = rx - (float)ix0;
            float wyv[4] = {cubw(fy+1.0f), cubw(fy), cubw(1.0f-fy), cubw(2.0f-fy)};
            float wxv[4] = {cubw(fx+1.0f), cubw(fx), cubw(1.0f-fx), cubw(2.0f-fx)};
            const float* ch = ref + ((size_t)b*64 + c)*4096;
#pragma unroll
            for (int u = 0; u < 4; u++) {
                int yy = min(max(iy0 - 1 + u, 0), 63);
                const float* rowp = ch + yy*64;
                float racc = 0.0f;
#pragma unroll
                for (int v = 0; v < 4; v++)
                    racc = fmaf(wxv[v], rowp[min(max(ix0 - 1 + v, 0), 63)], racc);
                val = fmaf(wyv[u], racc, val);
            }
        }
        rv[pi][c] = val;
    }
    __syncthreads();
    for (int i = t; i < 768; i += 128) {
        int pi = i / 96, o = i % 96;
        int l2 = l2sh[pi];
        if (l2 < 0) continue;
        float acc = bsh[o];
#pragma unroll
        for (int c = 0; c < 64; c++) acc = fmaf(Wsh[o][c], rv[pi][c], acc);
        acc = acc >= 0.0f ? acc : a*acc;
        if (o < 32) g_m   [((size_t)b*32 + o)     *LPAD2 + l2] = acc;
        else        g_base[((size_t)b*64 + (o-32))*LPAD2 + l2] = acc;
    }
}

// ---------------- sq ----------------
__global__ void k_prep() {
    int l = blockIdx.x*128 + threadIdx.x;
    int b = blockIdx.y;
    if (l >= LPAD2) return;
    float a = 0.0f;
#pragma unroll
    for (int c = 0; c < 32; c++) {
        float v = g_m[((size_t)b*32 + c)*LPAD2 + l];
        a = fmaf(v, v, a);
    }
    g_sq[b*LPAD2 + l] = a;
}

// ---------------- invb ----------------
__global__ void k_invb() {
    int l = blockIdx.x*128 + threadIdx.x;
    int b = blockIdx.y;
    if (l >= LPAD2) return;
    int wd = 0, loc = 0;
    if      (l < 4356)                { wd=66; loc=l; }
    else if (l >= 4368  && l < 7849)  { wd=59; loc=l-4368; }
    else if (l >= 7856  && l < 10665) { wd=53; loc=l-7856; }
    else if (l >= 10672 && l < 12788) { wd=46; loc=l-10672; }
    else if (l >= 12800 && l < 14400) { wd=40; loc=l-12800; }
    float2 o = make_float2(0.0f, -1e30f);
    if (wd) {
        int y = loc / wd, x = loc - y*wd;
        if (y >= 1 && y <= wd-2 && x >= 1 && x <= wd-2) {
            float a = 0.0f;
#pragma unroll
            for (int dy = -1; dy <= 1; dy++)
#pragma unroll
                for (int dx = -1; dx <= 1; dx++)
                    a += g_sq[b*LPAD2 + l + dy*wd + dx];
            o = make_float2(10.0f / fmaxf(sqrtf(a), 1e-4f), 0.0f);
        }
    }
    ((float2*)g_invb)[(size_t)b*LPAD2 + l] = o;
}

// ---- fused G-GEMM + x-shift (vectorized interior loads) ----
#define GH_SMEM (130*132*4)
__global__ __launch_bounds__(256) void k_gemm_GH() {
    extern __shared__ float sm[];
    float* as = sm;
    float* bs = sm + 32*132;
    float* gs = sm;
    const int b  = blockIdx.z;
    const int om = blockIdx.y << 7, on = blockIdx.x << 7;
    const float* A  = g_mb + (size_t)b*32*NQ;
    const float* Bm = g_m  + (size_t)b*32*LPAD2;
    float* Hout = g_H + GUARD + (size_t)b*NQ*LPAD2;
    const int t = threadIdx.x;

#pragma unroll
    for (int j = 0; j < 4; j++) {
        int id = t + (j << 8);
        int row = id >> 5, c4 = (id & 31) << 2;
        *(float4*)&as[row*132 + c4] = *(const float4*)(A  + (size_t)row*NQ    + om + c4);
        *(float4*)&bs[row*132 + c4] = *(const float4*)(Bm + (size_t)row*LPAD2 + on + c4);
    }
    if (t < 128) {
        int mat = t >> 6, col = (t >> 5) & 1, k = t & 31;
        if (mat == 0) {
            int ga = col ? om + 128 : om - 1;
            as[k*132 + 128 + col] = (ga >= 0 && ga < NQ) ? A[(size_t)k*NQ + ga] : 0.0f;
        } else {
            int gb = col ? on + 128 : on - 1;
            bs[k*132 + 128 + col] = (gb >= 0 && gb < LPAD2) ? Bm[(size_t)k*LPAD2 + gb] : 0.0f;
        }
    }
    __syncthreads();

    const int ty = t >> 4, tx = t & 15;
    float acc[8][8] = {};
#pragma unroll
    for (int kk = 0; kk < 32; kk++) {
        float4 a0 = *(const float4*)&as[kk*132 + (ty << 3)];
        float4 a1 = *(const float4*)&as[kk*132 + (ty << 3) + 4];
        float4 b0 = *(const float4*)&bs[kk*132 + (tx << 3)];
        float4 b1 = *(const float4*)&bs[kk*132 + (tx << 3) + 4];
        float ra[8] = {a0.x,a0.y,a0.z,a0.w,a1.x,a1.y,a1.z,a1.w};
        float rb[8] = {b0.x,b0.y,b0.z,b0.w,b1.x,b1.y,b1.z,b1.w};
#pragma unroll
        for (int i = 0; i < 8; i++)
#pragma unroll
            for (int j = 0; j < 8; j++)
                acc[i][j] = fmaf(ra[i], rb[j], acc[i][j]);
    }

    float hv[3]; int hidx[3]; int nh = 0;
    for (int h = t; h < 516; h += 256) {
        int ai, bi, gr, gc;
        if (h < 130)      { gr = 128; int hh = h;     gc = (hh==0)?128:((hh==129)?129:hh-1); ai = 128; bi = gc; }
        else if (h < 260) { gr = 129; int hh = h-130; gc = (hh==0)?128:((hh==129)?129:hh-1); ai = 129; bi = gc; }
        else if (h < 388) { gr = h-260; gc = 128; ai = gr; bi = 128; }
        else              { gr = h-388; gc = 129; ai = gr; bi = 129; }
        float s = 0.0f;
#pragma unroll
        for (int k = 0; k < 32; k++) s = fmaf(as[k*132 + ai], bs[k*132 + bi], s);
        hv[nh] = s; hidx[nh] = gr*132 + gc; nh++;
    }
    __syncthreads();

#pragma unroll
    for (int i = 0; i < 8; i++) {
        float* gr = gs + (ty*8 + i)*132 + tx*8;
        *(float4*)gr     = make_float4(acc[i][0],acc[i][1],acc[i][2],acc[i][3]);
        *(float4*)(gr+4) = make_float4(acc[i][4],acc[i][5],acc[i][6],acc[i][7]);
    }
    for (int n = 0; n < nh; n++) gs[hidx[n]] = hv[n];
    __syncthreads();

#pragma unroll
    for (int i = 0; i < 8; i++) {
        int row = ty*8 + i;
        int x = row & 63;
        bool mm = x > 0, mp = x < 63;
        int rm = (row == 0)   ? 128 : row - 1;
        int rp = (row == 127) ? 129 : row + 1;
        float hv8[8];
#pragma unroll
        for (int j = 0; j < 8; j++) {
            int col = tx*8 + j;
            int cm = (col == 0)   ? 128 : col - 1;
            int cp = (col == 127) ? 129 : col + 1;
            float v = gs[row*132 + col];
            if (mm) v += gs[rm*132 + cm];
            if (mp) v += gs[rp*132 + cp];
            hv8[j] = v;
        }
        float* Dr = Hout + (size_t)(om + row)*LPAD2 + on + tx*8;
        *(float4*)Dr     = make_float4(hv8[0],hv8[1],hv8[2],hv8[3]);
        *(float4*)(Dr+4) = make_float4(hv8[4],hv8[5],hv8[6],hv8[7]);
    }
}

// ---------------- scoreV + softmax: H_G -> E + invs ----------------
__global__ __launch_bounds__(256) void k_scoreV() {
    int q = blockIdx.x, b = blockIdx.y;
    const float* S = g_H + GUARD + (size_t)b*NQ*LPAD2;
    float* D = g_P + GUARD + ((size_t)b*NQ + q)*LPAD2;
    const float2* ivb = ((const float2*)g_invb) + (size_t)b*LPAD2;
    int y = q >> 6, t = threadIdx.x;
    const float* up = S + (size_t)(q-64)*LPAD2;
    const float* md = S + (size_t)q*LPAD2;
    const float* dn = S + (size_t)(q+64)*LPAD2;
    bool uok = y > 0, dok = y < 63;
    float sreg[8][8];
    float mx = -3e38f;
#pragma unroll
    for (int it = 0; it < 8; it++) {
        int g = t + it*256;
        if (g >= NG8) break;
        int l8 = g << 3;
        int st = stride_of(l8);
        float acc[8], w[8];
        float4 m0 = *(const float4*)(md + l8), m1 = *(const float4*)(md + l8 + 4);
        acc[0]=m0.x; acc[1]=m0.y; acc[2]=m0.z; acc[3]=m0.w;
        acc[4]=m1.x; acc[5]=m1.y; acc[6]=m1.z; acc[7]=m1.w;
        if (uok) { ldwin8(up + l8 - st, w);
#pragma unroll
            for (int e = 0; e < 8; e++) acc[e] += w[e]; }
        if (dok) { ldwin8(dn + l8 + st, w);
#pragma unroll
            for (int e = 0; e < 8; e++) acc[e] += w[e]; }
#pragma unroll
        for (int k = 0; k < 4; k++) {
            float4 iv = *(const float4*)(ivb + l8 + 2*k);
            float s0 = fmaf(acc[2*k],   iv.x, iv.y);
            float s1 = fmaf(acc[2*k+1], iv.z, iv.w);
            sreg[it][2*k] = s0; sreg[it][2*k+1] = s1;
            mx = fmaxf(mx, fmaxf(s0, s1));
        }
    }
    __shared__ float red[8];
    __shared__ float bc;
#pragma unroll
    for (int o = 16; o > 0; o >>= 1) mx = fmaxf(mx, __shfl_xor_sync(0xffffffffu, mx, o));
    if ((t & 31) == 0) red[t >> 5] = mx;
    __syncthreads();
    if (t == 0) {
        float m = red[0];
#pragma unroll
        for (int i = 1; i < 8; i++) m = fmaxf(m, red[i]);
        bc = m;
    }
    __syncthreads();
    float M = bc, sum = 0.0f;
#pragma unroll
    for (int it = 0; it < 8; it++) {
        int g = t + it*256;
        if (g >= NG8) break;
        int l8 = g << 3;
        float e[8];
#pragma unroll
        for (int k = 0; k < 8; k++) { e[k] = fexp(sreg[it][k] - M); sum += e[k]; }
        *(float4*)(D + l8)     = make_float4(e[0],e[1],e[2],e[3]);
        *(float4*)(D + l8 + 4) = make_float4(e[4],e[5],e[6],e[7]);
    }
#pragma unroll
    for (int o = 16; o > 0; o >>= 1) sum += __shfl_xor_sync(0xffffffffu, sum, o);
    if ((t & 31) == 0) red[t >> 5] = sum;
    __syncthreads();
    if (t == 0) {
        float s = 0.0f;
#pragma unroll
        for (int i = 0; i < 8; i++) s += red[i];
        g_invs[b*NQ + q] = 1.0f / s;
    }
}

// ---------------- H_P = x-shift of E (scaled by invs) ----------------
__global__ __launch_bounds__(256) void k_HP() {
    int r = blockIdx.x, b = blockIdx.y;
    const float* S = g_P + GUARD + ((size_t)b*NQ + r)*LPAD2;
    float* D = g_G + GUARD + ((size_t)b*NQ + r)*LPAD2;
    int x = r & 63;
    bool lok = x > 0, rok = x < 63;
    float ivc = g_invs[b*NQ + r];
    float ivl = lok ? g_invs[b*NQ + r - 1] : 0.0f;
    float ivr = rok ? g_invs[b*NQ + r + 1] : 0.0f;
    for (int g = threadIdx.x; g < NG8; g += 256) {
        int l8 = g << 3;
        float acc[8], w[8];
        float4 c0 = *(const float4*)(S + l8), c1 = *(const float4*)(S + l8 + 4);
        acc[0]=ivc*c0.x; acc[1]=ivc*c0.y; acc[2]=ivc*c0.z; acc[3]=ivc*c0.w;
        acc[4]=ivc*c1.x; acc[5]=ivc*c1.y; acc[6]=ivc*c1.z; acc[7]=ivc*c1.w;
        if (lok) {
            ldwin8(S - LPAD2 + l8 - 1, w);
#pragma unroll
            for (int e = 0; e < 8; e++) acc[e] = fmaf(ivl, w[e], acc[e]);
        }
        if (rok) {
            ldwin8(S + LPAD2 + l8 + 1, w);
#pragma unroll
            for (int e = 0; e < 8; e++) acc[e] = fmaf(ivr, w[e], acc[e]);
        }
        *(float4*)(D + l8)     = make_float4(acc[0],acc[1],acc[2],acc[3]);
        *(float4*)(D + l8 + 4) = make_float4(acc[4],acc[5],acc[6],acc[7]);
    }
}

// ---- fused W-GEMM: A = y-shift of H_P built in the fill, out_part = W*base^T ----
__global__ __launch_bounds__(256) void k_gemm_W() {
    const int split = blockIdx.x;
    const int bm = blockIdx.y << 7;
    const int b  = blockIdx.z;
    const float* HP = g_G + GUARD + (size_t)b*NQ*LPAD2;
    const float* Bb = g_base + (size_t)b*64*LPAD2;
    __shared__ float As[8][128];
    __shared__ float Bs[8][64];
    const int t = threadIdx.x;
    const int ty = t >> 4, tx = t & 15;
    float acc[8][4] = {};
    const int kbeg = split * KSPL;
    const int arow = t >> 1, akc = (t & 1) << 2;
    const int q = bm + arow;
    const int yq = q >> 6;
    const bool uok = yq > 0, dok = yq < 63;
    const float* mdp = HP + (size_t)q*LPAD2 + akc;
    const float* upp = mdp - (size_t)64*LPAD2;
    const float* dnp = mdp + (size_t)64*LPAD2;
    const int brow = (t & 127) >> 1;
    const float* Bptr = Bb + (size_t)brow*LPAD2 + akc;
    for (int k0 = kbeg; k0 < kbeg + KSPL; k0 += 8) {
        int st = stride_of(k0);
        float4 a4 = *(const float4*)(mdp + k0);
        float aw[4] = {a4.x, a4.y, a4.z, a4.w};
        float w[4];
        if (uok) {
            ldwin4(upp, k0 - st, w);
#pragma unroll
            for (int e = 0; e < 4; e++) aw[e] += w[e];
        }
        if (dok) {
            ldwin4(dnp, k0 + st, w);
#pragma unroll
            for (int e = 0; e < 4; e++) aw[e] += w[e];
        }
        As[akc+0][arow] = aw[0]; As[akc+1][arow] = aw[1];
        As[akc+2][arow] = aw[2]; As[akc+3][arow] = aw[3];
        if (t < 128) {
            float4 b4 = *(const float4*)(Bptr + k0);
            Bs[akc+0][brow] = b4.x; Bs[akc+1][brow] = b4.y;
            Bs[akc+2][brow] = b4.z; Bs[akc+3][brow] = b4.w;
        }
        __syncthreads();
#pragma unroll
        for (int kk = 0; kk < 8; kk++) {
            float4 a0 = *(const float4*)&As[kk][ty << 3];
            float4 a1 = *(const float4*)&As[kk][(ty << 3) + 4];
            float4 b0 = *(const float4*)&Bs[kk][tx << 2];
            float ra[8] = {a0.x,a0.y,a0.z,a0.w,a1.x,a1.y,a1.z,a1.w};
            float rb[4] = {b0.x,b0.y,b0.z,b0.w};
#pragma unroll
            for (int i = 0; i < 8; i++)
#pragma unroll
                for (int j = 0; j < 4; j++)
                    acc[i][j] = fmaf(ra[i], rb[j], acc[i][j]);
        }
        __syncthreads();
    }
    float* pb = g_part + (size_t)(split*2 + b)*64*NQ;
#pragma unroll
    for (int j = 0; j < 4; j++) {
        int c = (tx << 2) + j;
        *(float4*)(pb + (size_t)c*NQ + bm + (ty << 3))     = make_float4(acc[0][j],acc[1][j],acc[2][j],acc[3][j]);
        *(float4*)(pb + (size_t)c*NQ + bm + (ty << 3) + 4) = make_float4(acc[4][j],acc[5][j],acc[6][j],acc[7][j]);
    }
}

// ---------------- reduce + residual ----------------
__global__ void k_final(const float* __restrict__ inp, float* __restrict__ out) {
    int idx = blockIdx.x * blockDim.x + threadIdx.x;
    if (idx >= 2*64*4096) return;
    int q = idx & 4095, c = (idx >> 12) & 63, b = idx >> 18;
    float s = 0.0f;
#pragma unroll
    for (int sp = 0; sp < NSPLIT; sp++)
        s += g_part[(size_t)(sp*2 + b)*64*NQ + (size_t)c*NQ + q];
    out[idx] = inp[idx] + 0.25f * s;
}

extern "C" void kernel_launch(void* const* d_in, const int* in_sizes, int n_in,
                              void* d_out, int out_size) {
    const float* input     = (const float*)d_in[0];
    const float* input_ref = (const float*)d_in[1];
    const float* Wb  = (const float*)d_in[2];
    const float* bbv = (const float*)d_in[3];
    const float* Wm  = (const float*)d_in[4];
    const float* bmv = (const float*)d_in[5];
    const float* Wa  = (const float*)d_in[6];
    const float* bav = (const float*)d_in[7];
    const float* ap  = (const float*)d_in[8];
    float* out = (float*)d_out;

    cudaFuncSetAttribute(k_gemm_GH, cudaFuncAttributeMaxDynamicSharedMemorySize, GH_SMEM);

    k_zero       <<<1024, 256>>>();
    k_matchbase  <<<1024, 256>>>(input, Wb, bbv, ap);
    k_resize_conv<<<dim3(1666, 2), 128>>>(input_ref, Wm, bmv, Wa, bav, ap);
    k_prep       <<<dim3(113, 2), 128>>>();
    k_invb       <<<dim3(113, 2), 128>>>();
    k_gemm_GH    <<<dim3(113, 32, 2), 256, GH_SMEM>>>(); // G-GEMM fused with x-shift -> H_G
    k_scoreV     <<<dim3(NQ, 2), 256>>>();               // scores -> E + invs
    k_HP         <<<dim3(NQ, 2), 256>>>();               // H_P = x-shift of E (scaled)
    k_gemm_W     <<<dim3(NSPLIT, 32, 2), 256>>>();       // fused y-shift + GEMM
    k_final      <<<2048, 256>>>(input, out);
}

// round 16
// speedup vs baseline: 1.2395x; 1.2395x over previous
#include <cuda_runtime.h>
#include <cuda_fp16.h>
#include <math.h>

#define LTOT  13326
#define LPAD2 14464
#define NQ    4096
#define GUARD 4096
#define NG8   (LPAD2/8)
#define NSPLIT 16
#define KSPL  (LPAD2/NSPLIT)   // 904

__constant__ int   c_off [5] = {0, 4096, 7345, 9946, 11882};
__constant__ int   c_off2[5] = {0, 4368, 7856, 10672, 12800};
__constant__ int   c_ws  [5] = {64, 57, 51, 44, 38};
__constant__ float c_ratio[5]= {1.0f, 63.0f/56.0f, 63.0f/50.0f, 63.0f/43.0f, 63.0f/37.0f};

__device__ __align__(16) float g_mb  [2*32*NQ];
__device__ __align__(16) float g_m   [(size_t)2*32*LPAD2];
__device__ __align__(16) float g_base[(size_t)2*64*LPAD2];
__device__ __align__(16) float g_sq  [2*LPAD2];
__device__ __align__(16) float g_invb[(size_t)2*2*LPAD2];            // (10/nrm, bias)
__device__ __align__(16) float g_G   [(size_t)2*NQ*LPAD2 + 2*GUARD]; // H_P lives here
__device__ __align__(16) float g_P   [(size_t)2*NQ*LPAD2 + 2*GUARD]; // E
__device__ __align__(16) float g_H   [(size_t)2*NQ*LPAD2 + 2*GUARD]; // H_G, then W (fp16)
__device__ __align__(16) float g_invs[2*NQ];
__device__ __align__(16) float g_part[(size_t)NSPLIT*2*64*NQ];

__device__ __forceinline__ float cubw(float d) {
    d = fabsf(d);
    if (d <= 1.0f) return ((1.25f*d - 2.25f)*d)*d + 1.0f;
    if (d <  2.0f) return ((-0.75f*d + 3.75f)*d - 6.0f)*d + 3.0f;
    return 0.0f;
}
__device__ __forceinline__ float fexp(float x) {
    float t = fmaxf(x * 1.4426950408889634f, -125.0f);
    int   ri = __float2int_rn(t);
    float f  = t - (float)ri;
    float z  = f * 0.6931471805599453f;
    float p  = 1.0f + z*(1.0f + z*(0.5f + z*(0.16666667f + z*(0.041666667f + z*0.0083333333f))));
    return __int_as_float((ri + 127) << 23) * p;
}
__device__ __forceinline__ void ldwin8(const float* p, float w[8]) {
    int d = (int)((((size_t)p) >> 2) & 3);
    const float4* ap = (const float4*)(p - d);
    float4 A = ap[0], B = ap[1], C = B;
    if (d) C = ap[2];
    if (d == 0)      { w[0]=A.x;w[1]=A.y;w[2]=A.z;w[3]=A.w;w[4]=B.x;w[5]=B.y;w[6]=B.z;w[7]=B.w; }
    else if (d == 1) { w[0]=A.y;w[1]=A.z;w[2]=A.w;w[3]=B.x;w[4]=B.y;w[5]=B.z;w[6]=B.w;w[7]=C.x; }
    else if (d == 2) { w[0]=A.z;w[1]=A.w;w[2]=B.x;w[3]=B.y;w[4]=B.z;w[5]=B.w;w[6]=C.x;w[7]=C.y; }
    else             { w[0]=A.w;w[1]=B.x;w[2]=B.y;w[3]=B.z;w[4]=B.w;w[5]=C.x;w[6]=C.y;w[7]=C.z; }
}
__device__ __forceinline__ int stride_of(int l) {
    if (l < 4368)  return 66;
    if (l < 7856)  return 59;
    if (l < 10672) return 53;
    if (l < 12800) return 46;
    return 40;
}

// ---------------- zero m/base ----------------
__global__ void k_zero() {
    size_t i = (size_t)blockIdx.x*blockDim.x + threadIdx.x;
    size_t nm = (size_t)2*32*LPAD2/4, nb = (size_t)2*64*LPAD2/4;
    float4 z = make_float4(0.f,0.f,0.f,0.f);
    for (; i < nm + nb; i += (size_t)gridDim.x*blockDim.x) {
        if (i < nm) ((float4*)g_m)[i] = z;
        else ((float4*)g_base)[i - nm] = z;
    }
}

// ---------------- match_base ----------------
__global__ void k_matchbase(const float* __restrict__ inp, const float* __restrict__ Wb,
                            const float* __restrict__ bb, const float* __restrict__ ap) {
    int idx = blockIdx.x * blockDim.x + threadIdx.x;
    if (idx >= 2*32*4096) return;
    int pos = idx & 4095, cm = (idx >> 12) & 31, b = idx >> 17;
    const float* x = inp + ((size_t)b*64)*4096 + pos;
    const float* w = Wb + cm*64;
    float acc = bb[cm];
#pragma unroll
    for (int c = 0; c < 64; c++) acc = fmaf(w[c], x[(size_t)c*4096], acc);
    float a = ap[0];
    g_mb[idx] = acc >= 0.0f ? acc : a*acc;
}

// ---------------- resize + conv (padded layout) ----------------
__global__ __launch_bounds__(128) void k_resize_conv(const float* __restrict__ ref,
        const float* __restrict__ Wm, const float* __restrict__ bmv,
        const float* __restrict__ Wa, const float* __restrict__ bav,
        const float* __restrict__ ap) {
    __shared__ float Wsh[96][65];
    __shared__ float bsh[96];
    __shared__ float rv[8][65];
    __shared__ int   l2sh[8];
    int b = blockIdx.y, t = threadIdx.x;
    for (int i = t; i < 96*64; i += 128) {
        int o = i >> 6, c = i & 63;
        Wsh[o][c] = (o < 32) ? Wm[o*64 + c] : Wa[(o-32)*64 + c];
    }
    if (t < 96) bsh[t] = (t < 32) ? bmv[t] : bav[t-32];
    float a = ap[0];
    int p0 = blockIdx.x * 8;
    if (t < 8) {
        int pos = p0 + t, v = -1;
        if (pos < LTOT) {
            int s = 0;
            while (s < 4 && pos >= c_off[s+1]) s++;
            int ws = c_ws[s], lp = pos - c_off[s];
            int y = lp / ws, x = lp - y*ws;
            v = c_off2[s] + (y+1)*(ws+2) + (x+1);
        }
        l2sh[t] = v;
    }
    for (int i = t; i < 512; i += 128) {
        int c = i >> 3, pi = i & 7;
        int pos = p0 + pi;
        float val = 0.0f;
        if (pos < LTOT) {
            int s = 0;
            while (s < 4 && pos >= c_off[s+1]) s++;
            int lp = pos - c_off[s];
            int ws = c_ws[s];
            int y = lp / ws, x = lp - y*ws;
            float ry = (float)y * c_ratio[s], rx = (float)x * c_ratio[s];
            int iy0 = (int)floorf(ry); float fy = ry - (float)iy0;
            int ix0 = (int)floorf(rx); float fx = rx - (float)ix0;
            float wyv[4] = {cubw(fy+1.0f), cubw(fy), cubw(1.0f-fy), cubw(2.0f-fy)};
            float wxv[4] = {cubw(fx+1.0f), cubw(fx), cubw(1.0f-fx), cubw(2.0f-fx)};
            const float* ch = ref + ((size_t)b*64 + c)*4096;
#pragma unroll
            for (int u = 0; u < 4; u++) {
                int yy = min(max(iy0 - 1 + u, 0), 63);
                const float* rowp = ch + yy*64;
                float racc = 0.0f;
#pragma unroll
                for (int v = 0; v < 4; v++)
                    racc = fmaf(wxv[v], rowp[min(max(ix0 - 1 + v, 0), 63)], racc);
                val = fmaf(wyv[u], racc, val);
            }
        }
        rv[pi][c] = val;
    }
    __syncthreads();
    for (int i = t; i < 768; i += 128) {
        int pi = i / 96, o = i % 96;
        int l2 = l2sh[pi];
        if (l2 < 0) continue;
        float acc = bsh[o];
#pragma unroll
        for (int c = 0; c < 64; c++) acc = fmaf(Wsh[o][c], rv[pi][c], acc);
        acc = acc >= 0.0f ? acc : a*acc;
        if (o < 32) g_m   [((size_t)b*32 + o)     *LPAD2 + l2] = acc;
        else        g_base[((size_t)b*64 + (o-32))*LPAD2 + l2] = acc;
    }
}

// ---------------- sq ----------------
__global__ void k_prep() {
    int l = blockIdx.x*128 + threadIdx.x;
    int b = blockIdx.y;
    if (l >= LPAD2) return;
    float a = 0.0f;
#pragma unroll
    for (int c = 0; c < 32; c++) {
        float v = g_m[((size_t)b*32 + c)*LPAD2 + l];
        a = fmaf(v, v, a);
    }
    g_sq[b*LPAD2 + l] = a;
}

// ---------------- invb ----------------
__global__ void k_invb() {
    int l = blockIdx.x*128 + threadIdx.x;
    int b = blockIdx.y;
    if (l >= LPAD2) return;
    int wd = 0, loc = 0;
    if      (l < 4356)                { wd=66; loc=l; }
    else if (l >= 4368  && l < 7849)  { wd=59; loc=l-4368; }
    else if (l >= 7856  && l < 10665) { wd=53; loc=l-7856; }
    else if (l >= 10672 && l < 12788) { wd=46; loc=l-10672; }
    else if (l >= 12800 && l < 14400) { wd=40; loc=l-12800; }
    float2 o = make_float2(0.0f, -1e30f);
    if (wd) {
        int y = loc / wd, x = loc - y*wd;
        if (y >= 1 && y <= wd-2 && x >= 1 && x <= wd-2) {
            float a = 0.0f;
#pragma unroll
            for (int dy = -1; dy <= 1; dy++)
#pragma unroll
                for (int dx = -1; dx <= 1; dx++)
                    a += g_sq[b*LPAD2 + l + dy*wd + dx];
            o = make_float2(10.0f / fmaxf(sqrtf(a), 1e-4f), 0.0f);
        }
    }
    ((float2*)g_invb)[(size_t)b*LPAD2 + l] = o;
}

// ---- fused G-GEMM + x-shift (vectorized interior loads) ----
#define GH_SMEM (130*132*4)
__global__ __launch_bounds__(256) void k_gemm_GH() {
    extern __shared__ float sm[];
    float* as = sm;
    float* bs = sm + 32*132;
    float* gs = sm;
    const int b  = blockIdx.z;
    const int om = blockIdx.y << 7, on = blockIdx.x << 7;
    const float* A  = g_mb + (size_t)b*32*NQ;
    const float* Bm = g_m  + (size_t)b*32*LPAD2;
    float* Hout = g_H + GUARD + (size_t)b*NQ*LPAD2;
    const int t = threadIdx.x;

#pragma unroll
    for (int j = 0; j < 4; j++) {
        int id = t + (j << 8);
        int row = id >> 5, c4 = (id & 31) << 2;
        *(float4*)&as[row*132 + c4] = *(const float4*)(A  + (size_t)row*NQ    + om + c4);
        *(float4*)&bs[row*132 + c4] = *(const float4*)(Bm + (size_t)row*LPAD2 + on + c4);
    }
    if (t < 128) {
        int mat = t >> 6, col = (t >> 5) & 1, k = t & 31;
        if (mat == 0) {
            int ga = col ? om + 128 : om - 1;
            as[k*132 + 128 + col] = (ga >= 0 && ga < NQ) ? A[(size_t)k*NQ + ga] : 0.0f;
        } else {
            int gb = col ? on + 128 : on - 1;
            bs[k*132 + 128 + col] = (gb >= 0 && gb < LPAD2) ? Bm[(size_t)k*LPAD2 + gb] : 0.0f;
        }
    }
    __syncthreads();

    const int ty = t >> 4, tx = t & 15;
    float acc[8][8] = {};
#pragma unroll
    for (int kk = 0; kk < 32; kk++) {
        float4 a0 = *(const float4*)&as[kk*132 + (ty << 3)];
        float4 a1 = *(const float4*)&as[kk*132 + (ty << 3) + 4];
        float4 b0 = *(const float4*)&bs[kk*132 + (tx << 3)];
        float4 b1 = *(const float4*)&bs[kk*132 + (tx << 3) + 4];
        float ra[8] = {a0.x,a0.y,a0.z,a0.w,a1.x,a1.y,a1.z,a1.w};
        float rb[8] = {b0.x,b0.y,b0.z,b0.w,b1.x,b1.y,b1.z,b1.w};
#pragma unroll
        for (int i = 0; i < 8; i++)
#pragma unroll
            for (int j = 0; j < 8; j++)
                acc[i][j] = fmaf(ra[i], rb[j], acc[i][j]);
    }

    float hv[3]; int hidx[3]; int nh = 0;
    for (int h = t; h < 516; h += 256) {
        int ai, bi, gr, gc;
        if (h < 130)      { gr = 128; int hh = h;     gc = (hh==0)?128:((hh==129)?129:hh-1); ai = 128; bi = gc; }
        else if (h < 260) { gr = 129; int hh = h-130; gc = (hh==0)?128:((hh==129)?129:hh-1); ai = 129; bi = gc; }
        else if (h < 388) { gr = h-260; gc = 128; ai = gr; bi = 128; }
        else              { gr = h-388; gc = 129; ai = gr; bi = 129; }
        float s = 0.0f;
#pragma unroll
        for (int k = 0; k < 32; k++) s = fmaf(as[k*132 + ai], bs[k*132 + bi], s);
        hv[nh] = s; hidx[nh] = gr*132 + gc; nh++;
    }
    __syncthreads();

#pragma unroll
    for (int i = 0; i < 8; i++) {
        float* gr = gs + (ty*8 + i)*132 + tx*8;
        *(float4*)gr     = make_float4(acc[i][0],acc[i][1],acc[i][2],acc[i][3]);
        *(float4*)(gr+4) = make_float4(acc[i][4],acc[i][5],acc[i][6],acc[i][7]);
    }
    for (int n = 0; n < nh; n++) gs[hidx[n]] = hv[n];
    __syncthreads();

#pragma unroll
    for (int i = 0; i < 8; i++) {
        int row = ty*8 + i;
        int x = row & 63;
        bool mm = x > 0, mp = x < 63;
        int rm = (row == 0)   ? 128 : row - 1;
        int rp = (row == 127) ? 129 : row + 1;
        float hv8[8];
#pragma unroll
        for (int j = 0; j < 8; j++) {
            int col = tx*8 + j;
            int cm = (col == 0)   ? 128 : col - 1;
            int cp = (col == 127) ? 129 : col + 1;
            float v = gs[row*132 + col];
            if (mm) v += gs[rm*132 + cm];
            if (mp) v += gs[rp*132 + cp];
            hv8[j] = v;
        }
        float* Dr = Hout + (size_t)(om + row)*LPAD2 + on + tx*8;
        *(float4*)Dr     = make_float4(hv8[0],hv8[1],hv8[2],hv8[3]);
        *(float4*)(Dr+4) = make_float4(hv8[4],hv8[5],hv8[6],hv8[7]);
    }
}

// ---------------- scoreV + softmax: H_G -> E + invs ----------------
__global__ __launch_bounds__(256) void k_scoreV() {
    int q = blockIdx.x, b = blockIdx.y;
    const float* S = g_H + GUARD + (size_t)b*NQ*LPAD2;
    float* D = g_P + GUARD + ((size_t)b*NQ + q)*LPAD2;
    const float2* ivb = ((const float2*)g_invb) + (size_t)b*LPAD2;
    int y = q >> 6, t = threadIdx.x;
    const float* up = S + (size_t)(q-64)*LPAD2;
    const float* md = S + (size_t)q*LPAD2;
    const float* dn = S + (size_t)(q+64)*LPAD2;
    bool uok = y > 0, dok = y < 63;
    float sreg[8][8];
    float mx = -3e38f;
#pragma unroll
    for (int it = 0; it < 8; it++) {
        int g = t + it*256;
        if (g >= NG8) break;
        int l8 = g << 3;
        int st = stride_of(l8);
        float acc[8], w[8];
        float4 m0 = *(const float4*)(md + l8), m1 = *(const float4*)(md + l8 + 4);
        acc[0]=m0.x; acc[1]=m0.y; acc[2]=m0.z; acc[3]=m0.w;
        acc[4]=m1.x; acc[5]=m1.y; acc[6]=m1.z; acc[7]=m1.w;
        if (uok) { ldwin8(up + l8 - st, w);
#pragma unroll
            for (int e = 0; e < 8; e++) acc[e] += w[e]; }
        if (dok) { ldwin8(dn + l8 + st, w);
#pragma unroll
            for (int e = 0; e < 8; e++) acc[e] += w[e]; }
#pragma unroll
        for (int k = 0; k < 4; k++) {
            float4 iv = *(const float4*)(ivb + l8 + 2*k);
            float s0 = fmaf(acc[2*k],   iv.x, iv.y);
            float s1 = fmaf(acc[2*k+1], iv.z, iv.w);
            sreg[it][2*k] = s0; sreg[it][2*k+1] = s1;
            mx = fmaxf(mx, fmaxf(s0, s1));
        }
    }
    __shared__ float red[8];
    __shared__ float bc;
#pragma unroll
    for (int o = 16; o > 0; o >>= 1) mx = fmaxf(mx, __shfl_xor_sync(0xffffffffu, mx, o));
    if ((t & 31) == 0) red[t >> 5] = mx;
    __syncthreads();
    if (t == 0) {
        float m = red[0];
#pragma unroll
        for (int i = 1; i < 8; i++) m = fmaxf(m, red[i]);
        bc = m;
    }
    __syncthreads();
    float M = bc, sum = 0.0f;
#pragma unroll
    for (int it = 0; it < 8; it++) {
        int g = t + it*256;
        if (g >= NG8) break;
        int l8 = g << 3;
        float e[8];
#pragma unroll
        for (int k = 0; k < 8; k++) { e[k] = fexp(sreg[it][k] - M); sum += e[k]; }
        *(float4*)(D + l8)     = make_float4(e[0],e[1],e[2],e[3]);
        *(float4*)(D + l8 + 4) = make_float4(e[4],e[5],e[6],e[7]);
    }
#pragma unroll
    for (int o = 16; o > 0; o >>= 1) sum += __shfl_xor_sync(0xffffffffu, sum, o);
    if ((t & 31) == 0) red[t >> 5] = sum;
    __syncthreads();
    if (t == 0) {
        float s = 0.0f;
#pragma unroll
        for (int i = 0; i < 8; i++) s += red[i];
        g_invs[b*NQ + q] = 1.0f / s;
    }
}

// ---------------- H_P = x-shift of E (scaled by invs) ----------------
__global__ __launch_bounds__(256) void k_HP() {
    int r = blockIdx.x, b = blockIdx.y;
    const float* S = g_P + GUARD + ((size_t)b*NQ + r)*LPAD2;
    float* D = g_G + GUARD + ((size_t)b*NQ + r)*LPAD2;
    int x = r & 63;
    bool lok = x > 0, rok = x < 63;
    float ivc = g_invs[b*NQ + r];
    float ivl = lok ? g_invs[b*NQ + r - 1] : 0.0f;
    float ivr = rok ? g_invs[b*NQ + r + 1] : 0.0f;
    for (int g = threadIdx.x; g < NG8; g += 256) {
        int l8 = g << 3;
        float acc[8], w[8];
        float4 c0 = *(const float4*)(S + l8), c1 = *(const float4*)(S + l8 + 4);
        acc[0]=ivc*c0.x; acc[1]=ivc*c0.y; acc[2]=ivc*c0.z; acc[3]=ivc*c0.w;
        acc[4]=ivc*c1.x; acc[5]=ivc*c1.y; acc[6]=ivc*c1.z; acc[7]=ivc*c1.w;
        if (lok) {
            ldwin8(S - LPAD2 + l8 - 1, w);
#pragma unroll
            for (int e = 0; e < 8; e++) acc[e] = fmaf(ivl, w[e], acc[e]);
        }
        if (rok) {
            ldwin8(S + LPAD2 + l8 + 1, w);
#pragma unroll
            for (int e = 0; e < 8; e++) acc[e] = fmaf(ivr, w[e], acc[e]);
        }
        *(float4*)(D + l8)     = make_float4(acc[0],acc[1],acc[2],acc[3]);
        *(float4*)(D + l8 + 4) = make_float4(acc[4],acc[5],acc[6],acc[7]);
    }
}

// ---------------- W = y-shift of H_P (fp16 output) ----------------
__global__ __launch_bounds__(256) void k_WV() {
    int q = blockIdx.x, b = blockIdx.y;
    const float* S = g_G + GUARD + (size_t)b*NQ*LPAD2;   // H_P
    __half* D = (__half*)g_H + ((size_t)b*NQ + q)*LPAD2; // W (fp16)
    int y = q >> 6;
    const float* up = S + (size_t)(q-64)*LPAD2;
    const float* md = S + (size_t)q*LPAD2;
    const float* dn = S + (size_t)(q+64)*LPAD2;
    bool uok = y > 0, dok = y < 63;
    for (int g = threadIdx.x; g < NG8; g += 256) {
        int l8 = g << 3;
        int st = stride_of(l8);
        float acc[8], w[8];
        float4 m0 = *(const float4*)(md + l8), m1 = *(const float4*)(md + l8 + 4);
        acc[0]=m0.x; acc[1]=m0.y; acc[2]=m0.z; acc[3]=m0.w;
        acc[4]=m1.x; acc[5]=m1.y; acc[6]=m1.z; acc[7]=m1.w;
        if (uok) { ldwin8(up + l8 - st, w);
#pragma unroll
            for (int e = 0; e < 8; e++) acc[e] += w[e]; }
        if (dok) { ldwin8(dn + l8 + st, w);
#pragma unroll
            for (int e = 0; e < 8; e++) acc[e] += w[e]; }
        union { __half2 h2[4]; uint4 u; } U;
        U.h2[0] = __floats2half2_rn(acc[0], acc[1]);
        U.h2[1] = __floats2half2_rn(acc[2], acc[3]);
        U.h2[2] = __floats2half2_rn(acc[4], acc[5]);
        U.h2[3] = __floats2half2_rn(acc[6], acc[7]);
        *(uint4*)(D + l8) = U.u;
    }
}

// ---------------- out_part = W(fp16) * base^T (split-K=16) ----------------
__global__ __launch_bounds__(256) void k_gemm_W() {
    const int split = blockIdx.x;
    const int bm = blockIdx.y << 7;
    const int b  = blockIdx.z;
    const __half* W = (const __half*)g_H + (size_t)b*NQ*LPAD2;
    const float* Bb = g_base + (size_t)b*64*LPAD2;
    __shared__ float As[8][128];
    __shared__ float Bs[8][64];
    const int t = threadIdx.x;
    const int ty = t >> 4, tx = t & 15;
    float acc[8][4] = {};
    const int kbeg = split * KSPL;
    const int arow = t >> 1, akc = (t & 1) << 2;
    const __half* Aptr = W + (size_t)(bm + arow)*LPAD2 + akc;
    const int brow = (t & 127) >> 1;
    const float* Bptr = Bb + (size_t)brow*LPAD2 + akc;
    for (int k0 = kbeg; k0 < kbeg + KSPL; k0 += 8) {
        uint2 av = *(const uint2*)(Aptr + k0);
        float2 f0 = __half22float2(*(__half2*)&av.x);
        float2 f1 = __half22float2(*(__half2*)&av.y);
        As[akc+0][arow] = f0.x; As[akc+1][arow] = f0.y;
        As[akc+2][arow] = f1.x; As[akc+3][arow] = f1.y;
        if (t < 128) {
            float4 b4 = *(const float4*)(Bptr + k0);
            Bs[akc+0][brow] = b4.x; Bs[akc+1][brow] = b4.y;
            Bs[akc+2][brow] = b4.z; Bs[akc+3][brow] = b4.w;
        }
        __syncthreads();
#pragma unroll
        for (int kk = 0; kk < 8; kk++) {
            float4 a0 = *(const float4*)&As[kk][ty << 3];
            float4 a1 = *(const float4*)&As[kk][(ty << 3) + 4];
            float4 b0 = *(const float4*)&Bs[kk][tx << 2];
            float ra[8] = {a0.x,a0.y,a0.z,a0.w,a1.x,a1.y,a1.z,a1.w};
            float rb[4] = {b0.x,b0.y,b0.z,b0.w};
#pragma unroll
            for (int i = 0; i < 8; i++)
#pragma unroll
                for (int j = 0; j < 4; j++)
                    acc[i][j] = fmaf(ra[i], rb[j], acc[i][j]);
        }
        __syncthreads();
    }
    float* pb = g_part + (size_t)(split*2 + b)*64*NQ;
#pragma unroll
    for (int j = 0; j < 4; j++) {
        int c = (tx << 2) + j;
        *(float4*)(pb + (size_t)c*NQ + bm + (ty << 3))     = make_float4(acc[0][j],acc[1][j],acc[2][j],acc[3][j]);
        *(float4*)(pb + (size_t)c*NQ + bm + (ty << 3) + 4) = make_float4(acc[4][j],acc[5][j],acc[6][j],acc[7][j]);
    }
}

// ---------------- reduce + residual ----------------
__global__ void k_final(const float* __restrict__ inp, float* __restrict__ out) {
    int idx = blockIdx.x * blockDim.x + threadIdx.x;
    if (idx >= 2*64*4096) return;
    int q = idx & 4095, c = (idx >> 12) & 63, b = idx >> 18;
    float s = 0.0f;
#pragma unroll
    for (int sp = 0; sp < NSPLIT; sp++)
        s += g_part[(size_t)(sp*2 + b)*64*NQ + (size_t)c*NQ + q];
    out[idx] = inp[idx] + 0.25f * s;
}

extern "C" void kernel_launch(void* const* d_in, const int* in_sizes, int n_in,
                              void* d_out, int out_size) {
    const float* input     = (const float*)d_in[0];
    const float* input_ref = (const float*)d_in[1];
    const float* Wb  = (const float*)d_in[2];
    const float* bbv = (const float*)d_in[3];
    const float* Wm  = (const float*)d_in[4];
    const float* bmv = (const float*)d_in[5];
    const float* Wa  = (const float*)d_in[6];
    const float* bav = (const float*)d_in[7];
    const float* ap  = (const float*)d_in[8];
    float* out = (float*)d_out;

    cudaFuncSetAttribute(k_gemm_GH, cudaFuncAttributeMaxDynamicSharedMemorySize, GH_SMEM);

    k_zero       <<<1024, 256>>>();
    k_matchbase  <<<1024, 256>>>(input, Wb, bbv, ap);
    k_resize_conv<<<dim3(1666, 2), 128>>>(input_ref, Wm, bmv, Wa, bav, ap);
    k_prep       <<<dim3(113, 2), 128>>>();
    k_invb       <<<dim3(113, 2), 128>>>();
    k_gemm_GH    <<<dim3(113, 32, 2), 256, GH_SMEM>>>(); // G-GEMM fused with x-shift -> H_G
    k_scoreV     <<<dim3(NQ, 2), 256>>>();               // scores -> E + invs
    k_HP         <<<dim3(NQ, 2), 256>>>();               // H_P = x-shift of E (scaled)
    k_WV         <<<dim3(NQ, 2), 256>>>();               // W = y-shift of H_P (fp16)
    k_gemm_W     <<<dim3(NSPLIT, 32, 2), 256>>>();
    k_final      <<<2048, 256>>>(input, out);
}

// round 17
// speedup vs baseline: 1.4328x; 1.1559x over previous
#include <cuda_runtime.h>
#include <cuda_fp16.h>
#include <math.h>

#define LTOT  13326
#define LPAD2 14464
#define NQ    4096
#define GUARD 4096
#define GUARDH 8192
#define NG8   (LPAD2/8)
#define NSPLIT 16
#define KSPL  (LPAD2/NSPLIT)   // 904

__constant__ int   c_off [5] = {0, 4096, 7345, 9946, 11882};
__constant__ int   c_off2[5] = {0, 4368, 7856, 10672, 12800};
__constant__ int   c_ws  [5] = {64, 57, 51, 44, 38};
__constant__ float c_ratio[5]= {1.0f, 63.0f/56.0f, 63.0f/50.0f, 63.0f/43.0f, 63.0f/37.0f};

__device__ __align__(16) float g_mb  [2*32*NQ];
__device__ __align__(16) float g_m   [(size_t)2*32*LPAD2];
__device__ __align__(16) float g_base[(size_t)2*64*LPAD2];
__device__ __align__(16) float g_sq  [2*LPAD2];
__device__ __align__(16) float g_invb[(size_t)2*2*LPAD2];            // (10/nrm, bias)
__device__ __align__(16) float g_G   [(size_t)2*NQ*LPAD2 + 2*GUARD]; // H_P (fp16) lives here
__device__ __align__(16) float g_P   [(size_t)2*NQ*LPAD2 + 2*GUARD]; // E (fp16)
__device__ __align__(16) float g_H   [(size_t)2*NQ*LPAD2 + 2*GUARD]; // H_G (fp32), then W (fp16)
__device__ __align__(16) float g_invs[2*NQ];
__device__ __align__(16) float g_part[(size_t)NSPLIT*2*64*NQ];

__device__ __forceinline__ float cubw(float d) {
    d = fabsf(d);
    if (d <= 1.0f) return ((1.25f*d - 2.25f)*d)*d + 1.0f;
    if (d <  2.0f) return ((-0.75f*d + 3.75f)*d - 6.0f)*d + 3.0f;
    return 0.0f;
}
__device__ __forceinline__ float fexp(float x) {
    float t = fmaxf(x * 1.4426950408889634f, -125.0f);
    int   ri = __float2int_rn(t);
    float f  = t - (float)ri;
    float z  = f * 0.6931471805599453f;
    float p  = 1.0f + z*(1.0f + z*(0.5f + z*(0.16666667f + z*(0.041666667f + z*0.0083333333f))));
    return __int_as_float((ri + 127) << 23) * p;
}
__device__ __forceinline__ void ldwin8(const float* p, float w[8]) {
    int d = (int)((((size_t)p) >> 2) & 3);
    const float4* ap = (const float4*)(p - d);
    float4 A = ap[0], B = ap[1], C = B;
    if (d) C = ap[2];
    if (d == 0)      { w[0]=A.x;w[1]=A.y;w[2]=A.z;w[3]=A.w;w[4]=B.x;w[5]=B.y;w[6]=B.z;w[7]=B.w; }
    else if (d == 1) { w[0]=A.y;w[1]=A.z;w[2]=A.w;w[3]=B.x;w[4]=B.y;w[5]=B.z;w[6]=B.w;w[7]=C.x; }
    else if (d == 2) { w[0]=A.z;w[1]=A.w;w[2]=B.x;w[3]=B.y;w[4]=B.z;w[5]=B.w;w[6]=C.x;w[7]=C.y; }
    else             { w[0]=A.w;w[1]=B.x;w[2]=B.y;w[3]=B.z;w[4]=B.w;w[5]=C.x;w[6]=C.y;w[7]=C.z; }
}
// unaligned 8-half window -> 8 floats
__device__ __forceinline__ void ldwin8h(const __half* p, float w[8]) {
    size_t addr = (size_t)p;
    int d = (int)((addr >> 1) & 7);
    const uint4* ap = (const uint4*)(addr & ~(size_t)15);
    uint4 A = ap[0], B = ap[1];
    unsigned y0, y1, y2, y3, y4;
    int j = d >> 1;
    if (j == 0)      { y0=A.x; y1=A.y; y2=A.z; y3=A.w; y4=B.x; }
    else if (j == 1) { y0=A.y; y1=A.z; y2=A.w; y3=B.x; y4=B.y; }
    else if (j == 2) { y0=A.z; y1=A.w; y2=B.x; y3=B.y; y4=B.z; }
    else             { y0=A.w; y1=B.x; y2=B.y; y3=B.z; y4=B.w; }
    unsigned sh = (unsigned)(d & 1) << 4;
    unsigned r0 = __funnelshift_r(y0, y1, sh);
    unsigned r1 = __funnelshift_r(y1, y2, sh);
    unsigned r2 = __funnelshift_r(y2, y3, sh);
    unsigned r3 = __funnelshift_r(y3, y4, sh);
    float2 f;
    f = __half22float2(*(__half2*)&r0); w[0]=f.x; w[1]=f.y;
    f = __half22float2(*(__half2*)&r1); w[2]=f.x; w[3]=f.y;
    f = __half22float2(*(__half2*)&r2); w[4]=f.x; w[5]=f.y;
    f = __half22float2(*(__half2*)&r3); w[6]=f.x; w[7]=f.y;
}
__device__ __forceinline__ void ld8h(const __half* p, float w[8]) {
    uint4 A = *(const uint4*)p;
    float2 f;
    f = __half22float2(*(__half2*)&A.x); w[0]=f.x; w[1]=f.y;
    f = __half22float2(*(__half2*)&A.y); w[2]=f.x; w[3]=f.y;
    f = __half22float2(*(__half2*)&A.z); w[4]=f.x; w[5]=f.y;
    f = __half22float2(*(__half2*)&A.w); w[6]=f.x; w[7]=f.y;
}
__device__ __forceinline__ void st8h(__half* p, const float w[8]) {
    union { __half2 h2[4]; uint4 u; } U;
    U.h2[0] = __floats2half2_rn(w[0], w[1]);
    U.h2[1] = __floats2half2_rn(w[2], w[3]);
    U.h2[2] = __floats2half2_rn(w[4], w[5]);
    U.h2[3] = __floats2half2_rn(w[6], w[7]);
    *(uint4*)p = U.u;
}
__device__ __forceinline__ int stride_of(int l) {
    if (l < 4368)  return 66;
    if (l < 7856)  return 59;
    if (l < 10672) return 53;
    if (l < 12800) return 46;
    return 40;
}

// ---------------- zero m/base ----------------
__global__ void k_zero() {
    size_t i = (size_t)blockIdx.x*blockDim.x + threadIdx.x;
    size_t nm = (size_t)2*32*LPAD2/4, nb = (size_t)2*64*LPAD2/4;
    float4 z = make_float4(0.f,0.f,0.f,0.f);
    for (; i < nm + nb; i += (size_t)gridDim.x*blockDim.x) {
        if (i < nm) ((float4*)g_m)[i] = z;
        else ((float4*)g_base)[i - nm] = z;
    }
}

// ---------------- match_base ----------------
__global__ void k_matchbase(const float* __restrict__ inp, const float* __restrict__ Wb,
                            const float* __restrict__ bb, const float* __restrict__ ap) {
    int idx = blockIdx.x * blockDim.x + threadIdx.x;
    if (idx >= 2*32*4096) return;
    int pos = idx & 4095, cm = (idx >> 12) & 31, b = idx >> 17;
    const float* x = inp + ((size_t)b*64)*4096 + pos;
    const float* w = Wb + cm*64;
    float acc = bb[cm];
#pragma unroll
    for (int c = 0; c < 64; c++) acc = fmaf(w[c], x[(size_t)c*4096], acc);
    float a = ap[0];
    g_mb[idx] = acc >= 0.0f ? acc : a*acc;
}

// ---------------- resize + conv (padded layout) ----------------
__global__ __launch_bounds__(128) void k_resize_conv(const float* __restrict__ ref,
        const float* __restrict__ Wm, const float* __restrict__ bmv,
        const float* __restrict__ Wa, const float* __restrict__ bav,
        const float* __restrict__ ap) {
    __shared__ float Wsh[96][65];
    __shared__ float bsh[96];
    __shared__ float rv[8][65];
    __shared__ int   l2sh[8];
    int b = blockIdx.y, t = threadIdx.x;
    for (int i = t; i < 96*64; i += 128) {
        int o = i >> 6, c = i & 63;
        Wsh[o][c] = (o < 32) ? Wm[o*64 + c] : Wa[(o-32)*64 + c];
    }
    if (t < 96) bsh[t] = (t < 32) ? bmv[t] : bav[t-32];
    float a = ap[0];
    int p0 = blockIdx.x * 8;
    if (t < 8) {
        int pos = p0 + t, v = -1;
        if (pos < LTOT) {
            int s = 0;
            while (s < 4 && pos >= c_off[s+1]) s++;
            int ws = c_ws[s], lp = pos - c_off[s];
            int y = lp / ws, x = lp - y*ws;
            v = c_off2[s] + (y+1)*(ws+2) + (x+1);
        }
        l2sh[t] = v;
    }
    for (int i = t; i < 512; i += 128) {
        int c = i >> 3, pi = i & 7;
        int pos = p0 + pi;
        float val = 0.0f;
        if (pos < LTOT) {
            int s = 0;
            while (s < 4 && pos >= c_off[s+1]) s++;
            int lp = pos - c_off[s];
            int ws = c_ws[s];
            int y = lp / ws, x = lp - y*ws;
            float ry = (float)y * c_ratio[s], rx = (float)x * c_ratio[s];
            int iy0 = (int)floorf(ry); float fy = ry - (float)iy0;
            int ix0 = (int)floorf(rx); float fx = rx - (float)ix0;
            float wyv[4] = {cubw(fy+1.0f), cubw(fy), cubw(1.0f-fy), cubw(2.0f-fy)};
            float wxv[4] = {cubw(fx+1.0f), cubw(fx), cubw(1.0f-fx), cubw(2.0f-fx)};
            const float* ch = ref + ((size_t)b*64 + c)*4096;
#pragma unroll
            for (int u = 0; u < 4; u++) {
                int yy = min(max(iy0 - 1 + u, 0), 63);
                const float* rowp = ch + yy*64;
                float racc = 0.0f;
#pragma unroll
                for (int v = 0; v < 4; v++)
                    racc = fmaf(wxv[v], rowp[min(max(ix0 - 1 + v, 0), 63)], racc);
                val = fmaf(wyv[u], racc, val);
            }
        }
        rv[pi][c] = val;
    }
    __syncthreads();
    for (int i = t; i < 768; i += 128) {
        int pi = i / 96, o = i % 96;
        int l2 = l2sh[pi];
        if (l2 < 0) continue;
        float acc = bsh[o];
#pragma unroll
        for (int c = 0; c < 64; c++) acc = fmaf(Wsh[o][c], rv[pi][c], acc);
        acc = acc >= 0.0f ? acc : a*acc;
        if (o < 32) g_m   [((size_t)b*32 + o)     *LPAD2 + l2] = acc;
        else        g_base[((size_t)b*64 + (o-32))*LPAD2 + l2] = acc;
    }
}

// ---------------- sq ----------------
__global__ void k_prep() {
    int l = blockIdx.x*128 + threadIdx.x;
    int b = blockIdx.y;
    if (l >= LPAD2) return;
    float a = 0.0f;
#pragma unroll
    for (int c = 0; c < 32; c++) {
        float v = g_m[((size_t)b*32 + c)*LPAD2 + l];
        a = fmaf(v, v, a);
    }
    g_sq[b*LPAD2 + l] = a;
}

// ---------------- invb ----------------
__global__ void k_invb() {
    int l = blockIdx.x*128 + threadIdx.x;
    int b = blockIdx.y;
    if (l >= LPAD2) return;
    int wd = 0, loc = 0;
    if      (l < 4356)                { wd=66; loc=l; }
    else if (l >= 4368  && l < 7849)  { wd=59; loc=l-4368; }
    else if (l >= 7856  && l < 10665) { wd=53; loc=l-7856; }
    else if (l >= 10672 && l < 12788) { wd=46; loc=l-10672; }
    else if (l >= 12800 && l < 14400) { wd=40; loc=l-12800; }
    float2 o = make_float2(0.0f, -1e30f);
    if (wd) {
        int y = loc / wd, x = loc - y*wd;
        if (y >= 1 && y <= wd-2 && x >= 1 && x <= wd-2) {
            float a = 0.0f;
#pragma unroll
            for (int dy = -1; dy <= 1; dy++)
#pragma unroll
                for (int dx = -1; dx <= 1; dx++)
                    a += g_sq[b*LPAD2 + l + dy*wd + dx];
            o = make_float2(10.0f / fmaxf(sqrtf(a), 1e-4f), 0.0f);
        }
    }
    ((float2*)g_invb)[(size_t)b*LPAD2 + l] = o;
}

// ---- fused G-GEMM + x-shift (vectorized interior loads) ----
#define GH_SMEM (130*132*4)
__global__ __launch_bounds__(256) void k_gemm_GH() {
    extern __shared__ float sm[];
    float* as = sm;
    float* bs = sm + 32*132;
    float* gs = sm;
    const int b  = blockIdx.z;
    const int om = blockIdx.y << 7, on = blockIdx.x << 7;
    const float* A  = g_mb + (size_t)b*32*NQ;
    const float* Bm = g_m  + (size_t)b*32*LPAD2;
    float* Hout = g_H + GUARD + (size_t)b*NQ*LPAD2;
    const int t = threadIdx.x;

#pragma unroll
    for (int j = 0; j < 4; j++) {
        int id = t + (j << 8);
        int row = id >> 5, c4 = (id & 31) << 2;
        *(float4*)&as[row*132 + c4] = *(const float4*)(A  + (size_t)row*NQ    + om + c4);
        *(float4*)&bs[row*132 + c4] = *(const float4*)(Bm + (size_t)row*LPAD2 + on + c4);
    }
    if (t < 128) {
        int mat = t >> 6, col = (t >> 5) & 1, k = t & 31;
        if (mat == 0) {
            int ga = col ? om + 128 : om - 1;
            as[k*132 + 128 + col] = (ga >= 0 && ga < NQ) ? A[(size_t)k*NQ + ga] : 0.0f;
        } else {
            int gb = col ? on + 128 : on - 1;
            bs[k*132 + 128 + col] = (gb >= 0 && gb < LPAD2) ? Bm[(size_t)k*LPAD2 + gb] : 0.0f;
        }
    }
    __syncthreads();

    const int ty = t >> 4, tx = t & 15;
    float acc[8][8] = {};
#pragma unroll
    for (int kk = 0; kk < 32; kk++) {
        float4 a0 = *(const float4*)&as[kk*132 + (ty << 3)];
        float4 a1 = *(const float4*)&as[kk*132 + (ty << 3) + 4];
        float4 b0 = *(const float4*)&bs[kk*132 + (tx << 3)];
        float4 b1 = *(const float4*)&bs[kk*132 + (tx << 3) + 4];
        float ra[8] = {a0.x,a0.y,a0.z,a0.w,a1.x,a1.y,a1.z,a1.w};
        float rb[8] = {b0.x,b0.y,b0.z,b0.w,b1.x,b1.y,b1.z,b1.w};
#pragma unroll
        for (int i = 0; i < 8; i++)
#pragma unroll
            for (int j = 0; j < 8; j++)
                acc[i][j] = fmaf(ra[i], rb[j], acc[i][j]);
    }

    float hv[3]; int hidx[3]; int nh = 0;
    for (int h = t; h < 516; h += 256) {
        int ai, bi, gr, gc;
        if (h < 130)      { gr = 128; int hh = h;     gc = (hh==0)?128:((hh==129)?129:hh-1); ai = 128; bi = gc; }
        else if (h < 260) { gr = 129; int hh = h-130; gc = (hh==0)?128:((hh==129)?129:hh-1); ai = 129; bi = gc; }
        else if (h < 388) { gr = h-260; gc = 128; ai = gr; bi = 128; }
        else              { gr = h-388; gc = 129; ai = gr; bi = 129; }
        float s = 0.0f;
#pragma unroll
        for (int k = 0; k < 32; k++) s = fmaf(as[k*132 + ai], bs[k*132 + bi], s);
        hv[nh] = s; hidx[nh] = gr*132 + gc; nh++;
    }
    __syncthreads();

#pragma unroll
    for (int i = 0; i < 8; i++) {
        float* gr = gs + (ty*8 + i)*132 + tx*8;
        *(float4*)gr     = make_float4(acc[i][0],acc[i][1],acc[i][2],acc[i][3]);
        *(float4*)(gr+4) = make_float4(acc[i][4],acc[i][5],acc[i][6],acc[i][7]);
    }
    for (int n = 0; n < nh; n++) gs[hidx[n]] = hv[n];
    __syncthreads();

#pragma unroll
    for (int i = 0; i < 8; i++) {
        int row = ty*8 + i;
        int x = row & 63;
        bool mm = x > 0, mp = x < 63;
        int rm = (row == 0)   ? 128 : row - 1;
        int rp = (row == 127) ? 129 : row + 1;
        float hv8[8];
#pragma unroll
        for (int j = 0; j < 8; j++) {
            int col = tx*8 + j;
            int cm = (col == 0)   ? 128 : col - 1;
            int cp = (col == 127) ? 129 : col + 1;
            float v = gs[row*132 + col];
            if (mm) v += gs[rm*132 + cm];
            if (mp) v += gs[rp*132 + cp];
            hv8[j] = v;
        }
        float* Dr = Hout + (size_t)(om + row)*LPAD2 + on + tx*8;
        *(float4*)Dr     = make_float4(hv8[0],hv8[1],hv8[2],hv8[3]);
        *(float4*)(Dr+4) = make_float4(hv8[4],hv8[5],hv8[6],hv8[7]);
    }
}

// ---------------- scoreV + softmax: H_G -> E(fp16) + invs ----------------
__global__ __launch_bounds__(256) void k_scoreV() {
    int q = blockIdx.x, b = blockIdx.y;
    const float* S = g_H + GUARD + (size_t)b*NQ*LPAD2;
    __half* D = (__half*)g_P + GUARDH + ((size_t)b*NQ + q)*LPAD2;
    const float2* ivb = ((const float2*)g_invb) + (size_t)b*LPAD2;
    int y = q >> 6, t = threadIdx.x;
    const float* up = S + (size_t)(q-64)*LPAD2;
    const float* md = S + (size_t)q*LPAD2;
    const float* dn = S + (size_t)(q+64)*LPAD2;
    bool uok = y > 0, dok = y < 63;
    float sreg[8][8];
    float mx = -3e38f;
#pragma unroll
    for (int it = 0; it < 8; it++) {
        int g = t + it*256;
        if (g >= NG8) break;
        int l8 = g << 3;
        int st = stride_of(l8);
        float acc[8], w[8];
        float4 m0 = *(const float4*)(md + l8), m1 = *(const float4*)(md + l8 + 4);
        acc[0]=m0.x; acc[1]=m0.y; acc[2]=m0.z; acc[3]=m0.w;
        acc[4]=m1.x; acc[5]=m1.y; acc[6]=m1.z; acc[7]=m1.w;
        if (uok) { ldwin8(up + l8 - st, w);
#pragma unroll
            for (int e = 0; e < 8; e++) acc[e] += w[e]; }
        if (dok) { ldwin8(dn + l8 + st, w);
#pragma unroll
            for (int e = 0; e < 8; e++) acc[e] += w[e]; }
#pragma unroll
        for (int k = 0; k < 4; k++) {
            float4 iv = *(const float4*)(ivb + l8 + 2*k);
            float s0 = fmaf(acc[2*k],   iv.x, iv.y);
            float s1 = fmaf(acc[2*k+1], iv.z, iv.w);
            sreg[it][2*k] = s0; sreg[it][2*k+1] = s1;
            mx = fmaxf(mx, fmaxf(s0, s1));
        }
    }
    __shared__ float red[8];
    __shared__ float bc;
#pragma unroll
    for (int o = 16; o > 0; o >>= 1) mx = fmaxf(mx, __shfl_xor_sync(0xffffffffu, mx, o));
    if ((t & 31) == 0) red[t >> 5] = mx;
    __syncthreads();
    if (t == 0) {
        float m = red[0];
#pragma unroll
        for (int i = 1; i < 8; i++) m = fmaxf(m, red[i]);
        bc = m;
    }
    __syncthreads();
    float M = bc, sum = 0.0f;
#pragma unroll
    for (int it = 0; it < 8; it++) {
        int g = t + it*256;
        if (g >= NG8) break;
        int l8 = g << 3;
        float e[8];
#pragma unroll
        for (int k = 0; k < 8; k++) { e[k] = fexp(sreg[it][k] - M); sum += e[k]; }
        st8h(D + l8, e);
    }
#pragma unroll
    for (int o = 16; o > 0; o >>= 1) sum += __shfl_xor_sync(0xffffffffu, sum, o);
    if ((t & 31) == 0) red[t >> 5] = sum;
    __syncthreads();
    if (t == 0) {
        float s = 0.0f;
#pragma unroll
        for (int i = 0; i < 8; i++) s += red[i];
        g_invs[b*NQ + q] = 1.0f / s;
    }
}

// ---------------- H_P(fp16) = x-shift of E(fp16), scaled by invs ----------------
__global__ __launch_bounds__(256) void k_HP() {
    int r = blockIdx.x, b = blockIdx.y;
    const __half* S = (const __half*)g_P + GUARDH + ((size_t)b*NQ + r)*LPAD2;
    __half* D = (__half*)g_G + GUARDH + ((size_t)b*NQ + r)*LPAD2;
    int x = r & 63;
    bool lok = x > 0, rok = x < 63;
    float ivc = g_invs[b*NQ + r];
    float ivl = lok ? g_invs[b*NQ + r - 1] : 0.0f;
    float ivr = rok ? g_invs[b*NQ + r + 1] : 0.0f;
    for (int g = threadIdx.x; g < NG8; g += 256) {
        int l8 = g << 3;
        float acc[8], c[8], w[8];
        ld8h(S + l8, c);
#pragma unroll
        for (int e = 0; e < 8; e++) acc[e] = ivc * c[e];
        if (lok) {
            ldwin8h(S - LPAD2 + l8 - 1, w);
#pragma unroll
            for (int e = 0; e < 8; e++) acc[e] = fmaf(ivl, w[e], acc[e]);
        }
        if (rok) {
            ldwin8h(S + LPAD2 + l8 + 1, w);
#pragma unroll
            for (int e = 0; e < 8; e++) acc[e] = fmaf(ivr, w[e], acc[e]);
        }
        st8h(D + l8, acc);
    }
}

// ---------------- W(fp16) = y-shift of H_P(fp16) ----------------
__global__ __launch_bounds__(256) void k_WV() {
    int q = blockIdx.x, b = blockIdx.y;
    const __half* S = (const __half*)g_G + GUARDH + (size_t)b*NQ*LPAD2;  // H_P
    __half* D = (__half*)g_H + ((size_t)b*NQ + q)*LPAD2;                 // W
    int y = q >> 6;
    const __half* up = S + (size_t)(q-64)*LPAD2;
    const __half* md = S + (size_t)q*LPAD2;
    const __half* dn = S + (size_t)(q+64)*LPAD2;
    bool uok = y > 0, dok = y < 63;
    for (int g = threadIdx.x; g < NG8; g += 256) {
        int l8 = g << 3;
        int st = stride_of(l8);
        float acc[8], w[8];
        ld8h(md + l8, acc);
        if (uok) { ldwin8h(up + l8 - st, w);
#pragma unroll
            for (int e = 0; e < 8; e++) acc[e] += w[e]; }
        if (dok) { ldwin8h(dn + l8 + st, w);
#pragma unroll
            for (int e = 0; e < 8; e++) acc[e] += w[e]; }
        st8h(D + l8, acc);
    }
}

// ---------------- out_part = W(fp16) * base^T (split-K=16) ----------------
__global__ __launch_bounds__(256) void k_gemm_W() {
    const int split = blockIdx.x;
    const int bm = blockIdx.y << 7;
    const int b  = blockIdx.z;
    const __half* W = (const __half*)g_H + (size_t)b*NQ*LPAD2;
    const float* Bb = g_base + (size_t)b*64*LPAD2;
    __shared__ float As[8][128];
    __shared__ float Bs[8][64];
    const int t = threadIdx.x;
    const int ty = t >> 4, tx = t & 15;
    float acc[8][4] = {};
    const int kbeg = split * KSPL;
    const int arow = t >> 1, akc = (t & 1) << 2;
    const __half* Aptr = W + (size_t)(bm + arow)*LPAD2 + akc;
    const int brow = (t & 127) >> 1;
    const float* Bptr = Bb + (size_t)brow*LPAD2 + akc;
    for (int k0 = kbeg; k0 < kbeg + KSPL; k0 += 8) {
        uint2 av = *(const uint2*)(Aptr + k0);
        float2 f0 = __half22float2(*(__half2*)&av.x);
        float2 f1 = __half22float2(*(__half2*)&av.y);
        As[akc+0][arow] = f0.x; As[akc+1][arow] = f0.y;
        As[akc+2][arow] = f1.x; As[akc+3][arow] = f1.y;
        if (t < 128) {
            float4 b4 = *(const float4*)(Bptr + k0);
            Bs[akc+0][brow] = b4.x; Bs[akc+1][brow] = b4.y;
            Bs[akc+2][brow] = b4.z; Bs[akc+3][brow] = b4.w;
        }
        __syncthreads();
#pragma unroll
        for (int kk = 0; kk < 8; kk++) {
            float4 a0 = *(const float4*)&As[kk][ty << 3];
            float4 a1 = *(const float4*)&As[kk][(ty << 3) + 4];
            float4 b0 = *(const float4*)&Bs[kk][tx << 2];
            float ra[8] = {a0.x,a0.y,a0.z,a0.w,a1.x,a1.y,a1.z,a1.w};
            float rb[4] = {b0.x,b0.y,b0.z,b0.w};
#pragma unroll
            for (int i = 0; i < 8; i++)
#pragma unroll
                for (int j = 0; j < 4; j++)
                    acc[i][j] = fmaf(ra[i], rb[j], acc[i][j]);
        }
        __syncthreads();
    }
    float* pb = g_part + (size_t)(split*2 + b)*64*NQ;
#pragma unroll
    for (int j = 0; j < 4; j++) {
        int c = (tx << 2) + j;
        *(float4*)(pb + (size_t)c*NQ + bm + (ty << 3))     = make_float4(acc[0][j],acc[1][j],acc[2][j],acc[3][j]);
        *(float4*)(pb + (size_t)c*NQ + bm + (ty << 3) + 4) = make_float4(acc[4][j],acc[5][j],acc[6][j],acc[7][j]);
    }
}

// ---------------- reduce + residual ----------------
__global__ void k_final(const float* __restrict__ inp, float* __restrict__ out) {
    int idx = blockIdx.x * blockDim.x + threadIdx.x;
    if (idx >= 2*64*4096) return;
    int q = idx & 4095, c = (idx >> 12) & 63, b = idx >> 18;
    float s = 0.0f;
#pragma unroll
    for (int sp = 0; sp < NSPLIT; sp++)
        s += g_part[(size_t)(sp*2 + b)*64*NQ + (size_t)c*NQ + q];
    out[idx] = inp[idx] + 0.25f * s;
}

extern "C" void kernel_launch(void* const* d_in, const int* in_sizes, int n_in,
                              void* d_out, int out_size) {
    const float* input     = (const float*)d_in[0];
    const float* input_ref = (const float*)d_in[1];
    const float* Wb  = (const float*)d_in[2];
    const float* bbv = (const float*)d_in[3];
    const float* Wm  = (const float*)d_in[4];
    const float* bmv = (const float*)d_in[5];
    const float* Wa  = (const float*)d_in[6];
    const float* bav = (const float*)d_in[7];
    const float* ap  = (const float*)d_in[8];
    float* out = (float*)d_out;

    cudaFuncSetAttribute(k_gemm_GH, cudaFuncAttributeMaxDynamicSharedMemorySize, GH_SMEM);

    k_zero       <<<1024, 256>>>();
    k_matchbase  <<<1024, 256>>>(input, Wb, bbv, ap);
    k_resize_conv<<<dim3(1666, 2), 128>>>(input_ref, Wm, bmv, Wa, bav, ap);
    k_prep       <<<dim3(113, 2), 128>>>();
    k_invb       <<<dim3(113, 2), 128>>>();
    k_gemm_GH    <<<dim3(113, 32, 2), 256, GH_SMEM>>>(); // G-GEMM fused with x-shift -> H_G
    k_scoreV     <<<dim3(NQ, 2), 256>>>();               // scores -> E(fp16) + invs
    k_HP         <<<dim3(NQ, 2), 256>>>();               // H_P(fp16) = x-shift of E
    k_WV         <<<dim3(NQ, 2), 256>>>();               // W(fp16) = y-shift of H_P
    k_gemm_W     <<<dim3(NSPLIT, 32, 2), 256>>>();
    k_final      <<<2048, 256>>>(input, out);
}